// round 15
// baseline (speedup 1.0000x reference)
#include <cuda_runtime.h>
#include <cuda_bf16.h>
#include <cstdint>

#define NN    100000   // nodes
#define RR    32       // relations
#define EE    3200000  // edges
#define EMBD  128      // embedding dim
#define HH    32       // hidden dim
#define BBASES 16      // num bases
#define CC    16       // output classes

#define SCAN_BLOCKS ((NN + 1023) / 1024)   // 98

// -------- scratch (static device globals) --------
__device__ float g_deg[RR * NN];                 // 12.8 MB
__device__ float g_h1[NN * HH];                  // 12.8 MB
__device__ float g_yb[NN * (BBASES * HH)];       // 204.8 MB
__device__ int   g_cnt[NN];
__device__ int   g_off[NN + 1];
__device__ int   g_pos[NN];
__device__ int   g_bsum[SCAN_BLOCKS];
__device__ int2  g_ev[EE];                       // 25.6 MB
__device__ unsigned short g_b1h[512 * 128];      // 128 KB  W bf16 hi, j-major [j][k]
__device__ unsigned short g_b1l[512 * 128];      // 128 KB  W bf16 lo

__device__ __forceinline__ uint32_t smem_u32(const void* p) {
    uint32_t a;
    asm("{ .reg .u64 t; cvta.to.shared.u64 t, %1; cvt.u32.u64 %0, t; }" : "=r"(a) : "l"(p));
    return a;
}
#define CP_ASYNC16(dst, src) \
    asm volatile("cp.async.cg.shared.global [%0], [%1], 16;" :: "r"(dst), "l"(src) : "memory")
#define CP_ASYNC8(dst, src) \
    asm volatile("cp.async.ca.shared.global [%0], [%1], 8;" :: "r"(dst), "l"(src) : "memory")
#define CP_COMMIT() asm volatile("cp.async.commit_group;" ::: "memory")
#define CP_WAIT1()  asm volatile("cp.async.wait_group 1;" ::: "memory")

// ======================= small kernels ==========================
__global__ void k_init_edge() {
    int i = blockIdx.x * blockDim.x + threadIdx.x;
    int stride = gridDim.x * blockDim.x;
    for (int idx = i; idx < RR * NN; idx += stride) g_deg[idx] = 0.f;
    for (int idx = i; idx < NN; idx += stride) g_cnt[idx] = 0;
}

__global__ void k_init_node(const float* __restrict__ bias2, float* __restrict__ out) {
    int i = blockIdx.x * blockDim.x + threadIdx.x;
    int stride = gridDim.x * blockDim.x;
    for (int idx = i; idx < NN * HH; idx += stride) g_h1[idx] = 0.f;
    for (int idx = i; idx < NN * CC; idx += stride) out[idx] = bias2[idx & (CC - 1)];
}

// prep W: W[k][j] = bases1[b][k][h], j = b*32+h  ->  bf16 hi/lo, j-major [j][k]
__global__ void k_prepB(const float* __restrict__ bases1) {
    int i = blockIdx.x * blockDim.x + threadIdx.x;
    if (i >= 512 * 128) return;
    int j = i >> 7, k = i & 127;
    int b = j >> 5, h = j & 31;
    float v = bases1[(b * EMBD + k) * HH + h];
    __nv_bfloat16 hi = __float2bfloat16(v);
    float rem = v - __bfloat162float(hi);
    __nv_bfloat16 lo = __float2bfloat16(rem);
    g_b1h[i] = __bfloat16_as_ushort(hi);
    g_b1l[i] = __bfloat16_as_ushort(lo);
}

__global__ void k_deg(const int* __restrict__ rel, const int* __restrict__ fr,
                      const int* __restrict__ to) {
    int i = blockIdx.x * blockDim.x + threadIdx.x;
    int stride = gridDim.x * blockDim.x;
    for (int e = i; e < EE; e += stride) {
        atomicAdd(&g_deg[__ldcs(&rel[e]) * NN + __ldcs(&fr[e])], 1.0f);
        atomicAdd(&g_cnt[__ldcs(&to[e])], 1);
    }
}

__global__ void k_scan1() {
    __shared__ int s[1024];
    int tid = threadIdx.x;
    int i = blockIdx.x * 1024 + tid;
    int v = (i < NN) ? g_cnt[i] : 0;
    s[tid] = v;
    __syncthreads();
    #pragma unroll
    for (int d = 1; d < 1024; d <<= 1) {
        int t = (tid >= d) ? s[tid - d] : 0;
        __syncthreads();
        s[tid] += t;
        __syncthreads();
    }
    if (i < NN) g_off[i] = s[tid] - v;
    if (tid == 1023) g_bsum[blockIdx.x] = s[1023];
}

__global__ void k_scan2() {
    __shared__ int s[128];
    int tid = threadIdx.x;
    int v = (tid < SCAN_BLOCKS) ? g_bsum[tid] : 0;
    s[tid] = v;
    __syncthreads();
    #pragma unroll
    for (int d = 1; d < 128; d <<= 1) {
        int t = (tid >= d) ? s[tid - d] : 0;
        __syncthreads();
        s[tid] += t;
        __syncthreads();
    }
    if (tid < SCAN_BLOCKS) g_bsum[tid] = s[tid] - v;
}

__global__ void k_scan3() {
    int i = blockIdx.x * 1024 + threadIdx.x;
    if (i < NN) {
        int o = g_off[i] + g_bsum[i >> 10];
        g_off[i] = o;
        g_pos[i] = o;
    }
    if (i == 0) g_off[NN] = EE;
}

__global__ void k_scatter(const int* __restrict__ rel, const int* __restrict__ fr,
                          const int* __restrict__ to) {
    int i = blockIdx.x * blockDim.x + threadIdx.x;
    int stride = gridDim.x * blockDim.x;
    for (int e = i; e < EE; e += stride) {
        int r = __ldcs(&rel[e]), f = __ldcs(&fr[e]);
        int pos = atomicAdd(&g_pos[__ldcs(&to[e])], 1);
        float val = 1.0f / g_deg[r * NN + f];
        __stcs(&g_ev[pos], make_int2((r << 17) | f, __float_as_int(val)));
    }
}

// ============== HMMA GEMM: yb = emb @ W, bf16 double-split (hh+hl+lh) ==========
#define HMM_PAD   136
#define HMM_SMEM  (2 * 64 * HMM_PAD * 2 + 2 * 128 * HMM_PAD * 2)   // 104448 B

#define MMA16816(C, A_, B_) \
    asm volatile("mma.sync.aligned.m16n8k16.row.col.f32.bf16.bf16.f32 " \
        "{%0,%1,%2,%3}, {%4,%5,%6,%7}, {%8,%9}, {%0,%1,%2,%3};" \
        : "+f"((C)[0]), "+f"((C)[1]), "+f"((C)[2]), "+f"((C)[3]) \
        : "r"((A_)[0]), "r"((A_)[1]), "r"((A_)[2]), "r"((A_)[3]), \
          "r"((B_)[0]), "r"((B_)[1]))

__global__ void __launch_bounds__(256, 2) k_gemm_hmma(const float* __restrict__ A) {
    extern __shared__ unsigned short sm[];
    unsigned short* Ah = sm;                                    // 64x136
    unsigned short* Al = Ah + 64 * HMM_PAD;
    unsigned short* Bh = Al + 64 * HMM_PAD;                     // 128x136
    unsigned short* Bl = Bh + 128 * HMM_PAD;

    int tid = threadIdx.x;
    int mt = blockIdx.x >> 2;
    int jt = blockIdx.x & 3;
    int m0 = mt * 64;
    int j0 = jt * 128;

    #pragma unroll
    for (int i = 0; i < 8; i++) {
        int lin = tid + i * 256;
        int row = lin >> 5;
        int k = (lin & 31) << 2;
        int node = m0 + row;
        float4 v = make_float4(0.f, 0.f, 0.f, 0.f);
        if (node < NN) v = __ldcs((const float4*)(A + (size_t)node * EMBD + k));
        __nv_bfloat16 hx = __float2bfloat16(v.x), hy = __float2bfloat16(v.y);
        __nv_bfloat16 hz = __float2bfloat16(v.z), hw = __float2bfloat16(v.w);
        __nv_bfloat16 lx = __float2bfloat16(v.x - __bfloat162float(hx));
        __nv_bfloat16 ly = __float2bfloat16(v.y - __bfloat162float(hy));
        __nv_bfloat16 lz = __float2bfloat16(v.z - __bfloat162float(hz));
        __nv_bfloat16 lw = __float2bfloat16(v.w - __bfloat162float(hw));
        uint2 hp = make_uint2(
            (uint32_t)__bfloat16_as_ushort(hx) | ((uint32_t)__bfloat16_as_ushort(hy) << 16),
            (uint32_t)__bfloat16_as_ushort(hz) | ((uint32_t)__bfloat16_as_ushort(hw) << 16));
        uint2 lp = make_uint2(
            (uint32_t)__bfloat16_as_ushort(lx) | ((uint32_t)__bfloat16_as_ushort(ly) << 16),
            (uint32_t)__bfloat16_as_ushort(lz) | ((uint32_t)__bfloat16_as_ushort(lw) << 16));
        int o = row * HMM_PAD + k;
        *(uint2*)&Ah[o] = hp;
        *(uint2*)&Al[o] = lp;
    }
    #pragma unroll
    for (int i = 0; i < 8; i++) {
        int lin = tid + i * 256;
        int jr = lin >> 4;
        int k8 = (lin & 15) << 3;
        size_t src = (size_t)(j0 + jr) * 128 + k8;
        *(uint4*)&Bh[jr * HMM_PAD + k8] = *(const uint4*)&g_b1h[src];
        *(uint4*)&Bl[jr * HMM_PAD + k8] = *(const uint4*)&g_b1l[src];
    }
    __syncthreads();

    int lane = tid & 31, w = tid >> 5;
    int g = lane >> 2, tg = lane & 3;
    int mb = (w & 1) << 5;
    int nb = (w >> 1) << 5;

    float acc[2][4][4];
    #pragma unroll
    for (int ms = 0; ms < 2; ms++)
        #pragma unroll
        for (int ns = 0; ns < 4; ns++)
            #pragma unroll
            for (int q = 0; q < 4; q++) acc[ms][ns][q] = 0.f;

    #pragma unroll
    for (int ks = 0; ks < 8; ks++) {
        int k0 = ks * 16;
        uint32_t af[2][2][4];
        #pragma unroll
        for (int s = 0; s < 2; s++) {
            const unsigned short* Asrc = s ? Al : Ah;
            #pragma unroll
            for (int ms = 0; ms < 2; ms++) {
                int base = (mb + ms * 16 + g) * HMM_PAD + k0 + tg * 2;
                af[s][ms][0] = *(const uint32_t*)&Asrc[base];
                af[s][ms][1] = *(const uint32_t*)&Asrc[base + 8 * HMM_PAD];
                af[s][ms][2] = *(const uint32_t*)&Asrc[base + 8];
                af[s][ms][3] = *(const uint32_t*)&Asrc[base + 8 * HMM_PAD + 8];
            }
        }
        uint32_t bf[2][4][2];
        #pragma unroll
        for (int s = 0; s < 2; s++) {
            const unsigned short* Bsrc = s ? Bl : Bh;
            #pragma unroll
            for (int ns = 0; ns < 4; ns++) {
                int base = (nb + ns * 8 + g) * HMM_PAD + k0 + tg * 2;
                bf[s][ns][0] = *(const uint32_t*)&Bsrc[base];
                bf[s][ns][1] = *(const uint32_t*)&Bsrc[base + 8];
            }
        }
        #pragma unroll
        for (int ms = 0; ms < 2; ms++)
            #pragma unroll
            for (int ns = 0; ns < 4; ns++) {
                MMA16816(acc[ms][ns], af[0][ms], bf[0][ns]);   // hh
                MMA16816(acc[ms][ns], af[0][ms], bf[1][ns]);   // hl
                MMA16816(acc[ms][ns], af[1][ms], bf[0][ns]);   // lh
            }
    }

    #pragma unroll
    for (int ms = 0; ms < 2; ms++) {
        int row0 = m0 + mb + ms * 16 + g;
        #pragma unroll
        for (int ns = 0; ns < 4; ns++) {
            int col = j0 + nb + ns * 8 + tg * 2;
            if (row0 < NN)
                __stcs((float2*)&g_yb[(size_t)row0 * 512 + col],
                       make_float2(acc[ms][ns][0], acc[ms][ns][1]));
            if (row0 + 8 < NN)
                __stcs((float2*)&g_yb[(size_t)(row0 + 8) * 512 + col],
                       make_float2(acc[ms][ns][2], acc[ms][ns][3]));
        }
    }
}

// ======================= edge passes ==========================
__device__ __forceinline__ void red_add_v4(float* addr, float a, float b, float c, float d) {
    asm volatile("red.global.add.v4.f32 [%0], {%1, %2, %3, %4};"
                 :: "l"(addr), "f"(a), "f"(b), "f"(c), "f"(d) : "memory");
}

#define EMAX 96    // prefetch cap per node (Poisson(32): max deg over 100k ~ 70)

// pass1: double-buffered cp.async of yb row AND edge list; 12 blocks/SM
#define P1_GRID 1776
__global__ void __launch_bounds__(128) k_pass1p(const float* __restrict__ comps1) {
    __shared__ float sc1[RR * BBASES];
    __shared__ float syb[2][BBASES * HH];
    __shared__ float sxw[RR * HH];
    __shared__ int2  sev[2][EMAX];
    int tid = threadIdx.x;
    *(float4*)&sc1[tid << 2] = *(const float4*)&comps1[tid << 2];

    int lane = tid & 31;
    int w = tid >> 5;
    int sub = lane >> 3;
    int h4 = (lane & 7) << 2;
    int r_c = tid >> 2;
    int h0 = (tid & 3) << 3;

    // prefetch node 0 of this block
    int n0 = blockIdx.x;
    int start = g_off[n0], end = g_off[n0 + 1];
    CP_ASYNC16(smem_u32(&syb[0][tid << 2]), &g_yb[(size_t)n0 * 512 + (tid << 2)]);
    {
        int c = end - start; if (c > EMAX) c = EMAX;
        if (tid < c) CP_ASYNC8(smem_u32(&sev[0][tid]), &g_ev[start + tid]);
    }
    CP_COMMIT();

    int buf = 0;
    for (int n = n0; n < NN; n += gridDim.x) {
        // prefetch next node (safe: barrier at end of previous iteration)
        int n2 = n + gridDim.x;
        int start2 = 0, end2 = 0;
        if (n2 < NN) {
            start2 = g_off[n2]; end2 = g_off[n2 + 1];
            CP_ASYNC16(smem_u32(&syb[buf ^ 1][tid << 2]), &g_yb[(size_t)n2 * 512 + (tid << 2)]);
            int c2 = end2 - start2; if (c2 > EMAX) c2 = EMAX;
            if (tid < c2) CP_ASYNC8(smem_u32(&sev[buf ^ 1][tid]), &g_ev[start2 + tid]);
        }
        CP_COMMIT();
        CP_WAIT1();                 // current buf ready
        __syncthreads();

        float acc[8] = {};
        #pragma unroll
        for (int b = 0; b < BBASES; b++) {
            float c = sc1[r_c * BBASES + b];
            #pragma unroll
            for (int j = 0; j < 8; j++)
                acc[j] += c * syb[buf][b * HH + h0 + j];
        }
        #pragma unroll
        for (int j = 0; j < 8; j++) sxw[r_c * HH + h0 + j] = acc[j];
        __syncthreads();

        int cnt = end - start;
        for (int bi = (w << 2); bi < cnt; bi += 16) {
            int i = bi + sub;
            if (i < cnt) {
                int2 ev = (i < EMAX) ? sev[buf][i] : __ldcs(&g_ev[start + i]);
                int r = ev.x >> 17;
                int f = ev.x & 0x1FFFF;
                float val = __int_as_float(ev.y);
                float4 x = *(const float4*)&sxw[r * HH + h4];
                red_add_v4(&g_h1[f * HH + h4], val * x.x, val * x.y, val * x.z, val * x.w);
            }
        }
        __syncthreads();            // WAR fence: edge-loop reads done before next prefetch
        start = start2; end = end2; buf ^= 1;
    }
}

// pass2: double-buffered cp.async of h1 row AND edge list
#define P2_GRID 888
#define SB2_STRIDE 528
__global__ void __launch_bounds__(128) k_pass2p(const float* __restrict__ comps2,
                                                const float* __restrict__ bases2,
                                                const float* __restrict__ bias1,
                                                float* __restrict__ out) {
    __shared__ float sb2[BBASES * SB2_STRIDE];
    __shared__ float sc2[RR * BBASES];
    __shared__ float sbias[HH];
    __shared__ float sraw[2][HH];
    __shared__ float sh1[HH];
    __shared__ float st[BBASES * CC];
    __shared__ float sq[RR * CC];
    __shared__ int2  sev[2][EMAX];
    int tid = threadIdx.x;
    for (int i = tid; i < BBASES * HH * CC / 4; i += 128) {
        int b = (i << 2) >> 9;
        int o = (i << 2) & 511;
        *(float4*)&sb2[b * SB2_STRIDE + o] = *(const float4*)&bases2[b * 512 + o];
    }
    *(float4*)&sc2[tid << 2] = *(const float4*)&comps2[tid << 2];
    if (tid < HH) sbias[tid] = bias1[tid];

    int lane = tid & 31;
    int w = tid >> 5;
    int sub = lane >> 2;
    int c0 = (lane & 3) << 2;

    int n0 = blockIdx.x;
    int start = g_off[n0], end = g_off[n0 + 1];
    if (tid < 8) CP_ASYNC16(smem_u32(&sraw[0][tid << 2]), &g_h1[(size_t)n0 * HH + (tid << 2)]);
    {
        int c = end - start; if (c > EMAX) c = EMAX;
        if (tid < c) CP_ASYNC8(smem_u32(&sev[0][tid]), &g_ev[start + tid]);
    }
    CP_COMMIT();

    int buf = 0;
    for (int n = n0; n < NN; n += gridDim.x) {
        int n2 = n + gridDim.x;
        int start2 = 0, end2 = 0;
        if (n2 < NN) {
            start2 = g_off[n2]; end2 = g_off[n2 + 1];
            if (tid < 8) CP_ASYNC16(smem_u32(&sraw[buf ^ 1][tid << 2]),
                                    &g_h1[(size_t)n2 * HH + (tid << 2)]);
            int c2 = end2 - start2; if (c2 > EMAX) c2 = EMAX;
            if (tid < c2) CP_ASYNC8(smem_u32(&sev[buf ^ 1][tid]), &g_ev[start2 + tid]);
        }
        CP_COMMIT();
        CP_WAIT1();
        __syncthreads();

        if (tid < HH) sh1[tid] = fmaxf(sraw[buf][tid] + sbias[tid], 0.f);
        __syncthreads();
        {
            int i = tid;
            int b = i >> 4, c = i & 15;
            float a0 = 0.f, a1 = 0.f;
            int b2 = (i + 128) >> 4, c2 = (i + 128) & 15;
            #pragma unroll
            for (int h = 0; h < HH; h++) {
                float hv = sh1[h];
                a0 += hv * sb2[b * SB2_STRIDE + h * CC + c];
                a1 += hv * sb2[b2 * SB2_STRIDE + h * CC + c2];
            }
            st[i] = a0;
            st[i + 128] = a1;
        }
        __syncthreads();
        #pragma unroll
        for (int k = 0; k < 4; k++) {
            int i = tid + k * 128;
            int r = i >> 4, c = i & 15;
            float a = 0.f;
            #pragma unroll
            for (int b = 0; b < BBASES; b++)
                a += sc2[r * BBASES + b] * st[b * CC + c];
            sq[i] = a;
        }
        __syncthreads();

        int cnt = end - start;
        for (int bi = (w << 3); bi < cnt; bi += 32) {
            int i = bi + sub;
            if (i < cnt) {
                int2 ev = (i < EMAX) ? sev[buf][i] : __ldcs(&g_ev[start + i]);
                int r = ev.x >> 17;
                int f = ev.x & 0x1FFFF;
                float val = __int_as_float(ev.y);
                float4 q = *(const float4*)&sq[r * CC + c0];
                red_add_v4(&out[f * CC + c0], val * q.x, val * q.y, val * q.z, val * q.w);
            }
        }
        __syncthreads();            // WAR fence: edge-loop reads done before next prefetch
        start = start2; end = end2; buf ^= 1;
    }
}

// -------- host: forked-stream launch (graph-capturable) --------
static cudaStream_t s_gemm = nullptr, s_node = nullptr;
static cudaEvent_t  e_root = nullptr, e_root2 = nullptr, e_gemm = nullptr, e_node = nullptr;

extern "C" void kernel_launch(void* const* d_in, const int* in_sizes, int n_in,
                              void* d_out, int out_size) {
    const float* emb    = (const float*)d_in[0];
    const float* comps1 = (const float*)d_in[1];
    const float* bases1 = (const float*)d_in[2];
    const float* comps2 = (const float*)d_in[3];
    const float* bases2 = (const float*)d_in[4];
    const float* bias1  = (const float*)d_in[5];
    const float* bias2  = (const float*)d_in[6];
    const int*   rel    = (const int*)d_in[7];
    const int*   fr     = (const int*)d_in[8];
    const int*   to     = (const int*)d_in[9];
    float* out = (float*)d_out;

    if (!s_gemm) {   // first call = correctness run (not captured)
        cudaStreamCreateWithFlags(&s_gemm, cudaStreamNonBlocking);
        cudaStreamCreateWithFlags(&s_node, cudaStreamNonBlocking);
        cudaEventCreateWithFlags(&e_root,  cudaEventDisableTiming);
        cudaEventCreateWithFlags(&e_root2, cudaEventDisableTiming);
        cudaEventCreateWithFlags(&e_gemm,  cudaEventDisableTiming);
        cudaEventCreateWithFlags(&e_node,  cudaEventDisableTiming);
        cudaFuncSetAttribute(k_gemm_hmma, cudaFuncAttributeMaxDynamicSharedMemorySize, HMM_SMEM);
    }

    cudaEventRecord(e_root, 0);
    cudaStreamWaitEvent(s_gemm, e_root, 0);
    cudaEventRecord(e_root2, 0);
    cudaStreamWaitEvent(s_node, e_root2, 0);

    k_prepB<<<256, 256, 0, s_gemm>>>(bases1);                   // [1] (s_gemm)
    k_init_edge<<<8192, 256>>>();                               // [2] (default)
    k_init_node<<<4096, 256, 0, s_node>>>(bias2, out);          // [3] (s_node)
    k_gemm_hmma<<<1563 * 4, 256, HMM_SMEM, s_gemm>>>(emb);      // [4] PROFILED
    k_deg<<<4096, 256>>>(rel, fr, to);                          // [5] (default)
    k_scan1<<<SCAN_BLOCKS, 1024>>>();
    k_scan2<<<1, 128>>>();
    k_scan3<<<SCAN_BLOCKS, 1024>>>();
    k_scatter<<<4096, 256>>>(rel, fr, to);

    cudaEventRecord(e_gemm, s_gemm);
    cudaEventRecord(e_node, s_node);
    cudaStreamWaitEvent(0, e_gemm, 0);
    cudaStreamWaitEvent(0, e_node, 0);

    k_pass1p<<<P1_GRID, 128>>>(comps1);
    k_pass2p<<<P2_GRID, 128>>>(comps2, bases2, bias1, out);
}

// round 16
// speedup vs baseline: 1.3946x; 1.3946x over previous
#include <cuda_runtime.h>
#include <cuda_bf16.h>
#include <cstdint>

#define NN    100000   // nodes
#define RR    32       // relations
#define EE    3200000  // edges
#define EMBD  128      // embedding dim
#define HH    32       // hidden dim
#define BBASES 16      // num bases
#define CC    16       // output classes

#define SCAN_BLOCKS ((NN + 1023) / 1024)   // 98

// -------- scratch (static device globals) --------
__device__ float g_deg[RR * NN];                 // 12.8 MB
__device__ float g_h1[NN * HH];                  // 12.8 MB
__device__ float g_yb[NN * (BBASES * HH)];       // 204.8 MB
__device__ int   g_cnt[NN];
__device__ int   g_off[NN + 1];
__device__ int   g_pos[NN];
__device__ int   g_bsum[SCAN_BLOCKS];
__device__ int2  g_ev[EE];                       // 25.6 MB
__device__ unsigned short g_b1h[512 * 128];      // 128 KB  W bf16 hi, j-major [j][k]
__device__ unsigned short g_b1l[512 * 128];      // 128 KB  W bf16 lo

__device__ __forceinline__ uint32_t smem_u32(const void* p) {
    uint32_t a;
    asm("{ .reg .u64 t; cvta.to.shared.u64 t, %1; cvt.u32.u64 %0, t; }" : "=r"(a) : "l"(p));
    return a;
}
#define CP_ASYNC16(dst, src) \
    asm volatile("cp.async.cg.shared.global [%0], [%1], 16;" :: "r"(dst), "l"(src) : "memory")
#define CP_ASYNC8(dst, src) \
    asm volatile("cp.async.ca.shared.global [%0], [%1], 8;" :: "r"(dst), "l"(src) : "memory")
#define CP_COMMIT() asm volatile("cp.async.commit_group;" ::: "memory")
#define CP_WAIT1()  asm volatile("cp.async.wait_group 1;" ::: "memory")
#define CP_WAIT0()  asm volatile("cp.async.wait_group 0;" ::: "memory")

// ======================= small kernels ==========================
__global__ void k_init_edge() {
    int i = blockIdx.x * blockDim.x + threadIdx.x;
    int stride = gridDim.x * blockDim.x;
    for (int idx = i; idx < RR * NN; idx += stride) g_deg[idx] = 0.f;
    for (int idx = i; idx < NN; idx += stride) g_cnt[idx] = 0;
}

__global__ void k_init_node(const float* __restrict__ bias2, float* __restrict__ out) {
    int i = blockIdx.x * blockDim.x + threadIdx.x;
    int stride = gridDim.x * blockDim.x;
    for (int idx = i; idx < NN * HH; idx += stride) g_h1[idx] = 0.f;
    for (int idx = i; idx < NN * CC; idx += stride) out[idx] = bias2[idx & (CC - 1)];
}

// prep W: W[k][j] = bases1[b][k][h], j = b*32+h  ->  bf16 hi/lo, j-major [j][k]
__global__ void k_prepB(const float* __restrict__ bases1) {
    int i = blockIdx.x * blockDim.x + threadIdx.x;
    if (i >= 512 * 128) return;
    int j = i >> 7, k = i & 127;
    int b = j >> 5, h = j & 31;
    float v = bases1[(b * EMBD + k) * HH + h];
    __nv_bfloat16 hi = __float2bfloat16(v);
    float rem = v - __bfloat162float(hi);
    __nv_bfloat16 lo = __float2bfloat16(rem);
    g_b1h[i] = __bfloat16_as_ushort(hi);
    g_b1l[i] = __bfloat16_as_ushort(lo);
}

__global__ void k_deg(const int* __restrict__ rel, const int* __restrict__ fr,
                      const int* __restrict__ to) {
    int i = blockIdx.x * blockDim.x + threadIdx.x;
    int stride = gridDim.x * blockDim.x;
    for (int e = i; e < EE; e += stride) {
        atomicAdd(&g_deg[__ldcs(&rel[e]) * NN + __ldcs(&fr[e])], 1.0f);
        atomicAdd(&g_cnt[__ldcs(&to[e])], 1);
    }
}

__global__ void k_scan1() {
    __shared__ int s[1024];
    int tid = threadIdx.x;
    int i = blockIdx.x * 1024 + tid;
    int v = (i < NN) ? g_cnt[i] : 0;
    s[tid] = v;
    __syncthreads();
    #pragma unroll
    for (int d = 1; d < 1024; d <<= 1) {
        int t = (tid >= d) ? s[tid - d] : 0;
        __syncthreads();
        s[tid] += t;
        __syncthreads();
    }
    if (i < NN) g_off[i] = s[tid] - v;
    if (tid == 1023) g_bsum[blockIdx.x] = s[1023];
}

__global__ void k_scan2() {
    __shared__ int s[128];
    int tid = threadIdx.x;
    int v = (tid < SCAN_BLOCKS) ? g_bsum[tid] : 0;
    s[tid] = v;
    __syncthreads();
    #pragma unroll
    for (int d = 1; d < 128; d <<= 1) {
        int t = (tid >= d) ? s[tid - d] : 0;
        __syncthreads();
        s[tid] += t;
        __syncthreads();
    }
    if (tid < SCAN_BLOCKS) g_bsum[tid] = s[tid] - v;
}

__global__ void k_scan3() {
    int i = blockIdx.x * 1024 + threadIdx.x;
    if (i < NN) {
        int o = g_off[i] + g_bsum[i >> 10];
        g_off[i] = o;
        g_pos[i] = o;
    }
    if (i == 0) g_off[NN] = EE;
}

__global__ void k_scatter(const int* __restrict__ rel, const int* __restrict__ fr,
                          const int* __restrict__ to) {
    int i = blockIdx.x * blockDim.x + threadIdx.x;
    int stride = gridDim.x * blockDim.x;
    for (int e = i; e < EE; e += stride) {
        int r = __ldcs(&rel[e]), f = __ldcs(&fr[e]);
        int pos = atomicAdd(&g_pos[__ldcs(&to[e])], 1);
        float val = 1.0f / g_deg[r * NN + f];
        __stcs(&g_ev[pos], make_int2((r << 17) | f, __float_as_int(val)));
    }
}

// ============== HMMA GEMM: yb = emb @ W, bf16 double-split (hh+hl+lh) ==========
#define HMM_PAD   136
#define HMM_SMEM  (2 * 64 * HMM_PAD * 2 + 2 * 128 * HMM_PAD * 2)   // 104448 B

#define MMA16816(C, A_, B_) \
    asm volatile("mma.sync.aligned.m16n8k16.row.col.f32.bf16.bf16.f32 " \
        "{%0,%1,%2,%3}, {%4,%5,%6,%7}, {%8,%9}, {%0,%1,%2,%3};" \
        : "+f"((C)[0]), "+f"((C)[1]), "+f"((C)[2]), "+f"((C)[3]) \
        : "r"((A_)[0]), "r"((A_)[1]), "r"((A_)[2]), "r"((A_)[3]), \
          "r"((B_)[0]), "r"((B_)[1]))

__global__ void __launch_bounds__(256, 2) k_gemm_hmma(const float* __restrict__ A) {
    extern __shared__ unsigned short sm[];
    unsigned short* Ah = sm;                                    // 64x136
    unsigned short* Al = Ah + 64 * HMM_PAD;
    unsigned short* Bh = Al + 64 * HMM_PAD;                     // 128x136
    unsigned short* Bl = Bh + 128 * HMM_PAD;

    int tid = threadIdx.x;
    int mt = blockIdx.x >> 2;
    int jt = blockIdx.x & 3;
    int m0 = mt * 64;
    int j0 = jt * 128;

    #pragma unroll
    for (int i = 0; i < 8; i++) {
        int lin = tid + i * 256;
        int row = lin >> 5;
        int k = (lin & 31) << 2;
        int node = m0 + row;
        float4 v = make_float4(0.f, 0.f, 0.f, 0.f);
        if (node < NN) v = __ldcs((const float4*)(A + (size_t)node * EMBD + k));
        __nv_bfloat16 hx = __float2bfloat16(v.x), hy = __float2bfloat16(v.y);
        __nv_bfloat16 hz = __float2bfloat16(v.z), hw = __float2bfloat16(v.w);
        __nv_bfloat16 lx = __float2bfloat16(v.x - __bfloat162float(hx));
        __nv_bfloat16 ly = __float2bfloat16(v.y - __bfloat162float(hy));
        __nv_bfloat16 lz = __float2bfloat16(v.z - __bfloat162float(hz));
        __nv_bfloat16 lw = __float2bfloat16(v.w - __bfloat162float(hw));
        uint2 hp = make_uint2(
            (uint32_t)__bfloat16_as_ushort(hx) | ((uint32_t)__bfloat16_as_ushort(hy) << 16),
            (uint32_t)__bfloat16_as_ushort(hz) | ((uint32_t)__bfloat16_as_ushort(hw) << 16));
        uint2 lp = make_uint2(
            (uint32_t)__bfloat16_as_ushort(lx) | ((uint32_t)__bfloat16_as_ushort(ly) << 16),
            (uint32_t)__bfloat16_as_ushort(lz) | ((uint32_t)__bfloat16_as_ushort(lw) << 16));
        int o = row * HMM_PAD + k;
        *(uint2*)&Ah[o] = hp;
        *(uint2*)&Al[o] = lp;
    }
    #pragma unroll
    for (int i = 0; i < 8; i++) {
        int lin = tid + i * 256;
        int jr = lin >> 4;
        int k8 = (lin & 15) << 3;
        size_t src = (size_t)(j0 + jr) * 128 + k8;
        *(uint4*)&Bh[jr * HMM_PAD + k8] = *(const uint4*)&g_b1h[src];
        *(uint4*)&Bl[jr * HMM_PAD + k8] = *(const uint4*)&g_b1l[src];
    }
    __syncthreads();

    int lane = tid & 31, w = tid >> 5;
    int g = lane >> 2, tg = lane & 3;
    int mb = (w & 1) << 5;
    int nb = (w >> 1) << 5;

    float acc[2][4][4];
    #pragma unroll
    for (int ms = 0; ms < 2; ms++)
        #pragma unroll
        for (int ns = 0; ns < 4; ns++)
            #pragma unroll
            for (int q = 0; q < 4; q++) acc[ms][ns][q] = 0.f;

    #pragma unroll
    for (int ks = 0; ks < 8; ks++) {
        int k0 = ks * 16;
        uint32_t af[2][2][4];
        #pragma unroll
        for (int s = 0; s < 2; s++) {
            const unsigned short* Asrc = s ? Al : Ah;
            #pragma unroll
            for (int ms = 0; ms < 2; ms++) {
                int base = (mb + ms * 16 + g) * HMM_PAD + k0 + tg * 2;
                af[s][ms][0] = *(const uint32_t*)&Asrc[base];
                af[s][ms][1] = *(const uint32_t*)&Asrc[base + 8 * HMM_PAD];
                af[s][ms][2] = *(const uint32_t*)&Asrc[base + 8];
                af[s][ms][3] = *(const uint32_t*)&Asrc[base + 8 * HMM_PAD + 8];
            }
        }
        uint32_t bf[2][4][2];
        #pragma unroll
        for (int s = 0; s < 2; s++) {
            const unsigned short* Bsrc = s ? Bl : Bh;
            #pragma unroll
            for (int ns = 0; ns < 4; ns++) {
                int base = (nb + ns * 8 + g) * HMM_PAD + k0 + tg * 2;
                bf[s][ns][0] = *(const uint32_t*)&Bsrc[base];
                bf[s][ns][1] = *(const uint32_t*)&Bsrc[base + 8];
            }
        }
        #pragma unroll
        for (int ms = 0; ms < 2; ms++)
            #pragma unroll
            for (int ns = 0; ns < 4; ns++) {
                MMA16816(acc[ms][ns], af[0][ms], bf[0][ns]);   // hh
                MMA16816(acc[ms][ns], af[0][ms], bf[1][ns]);   // hl
                MMA16816(acc[ms][ns], af[1][ms], bf[0][ns]);   // lh
            }
    }

    #pragma unroll
    for (int ms = 0; ms < 2; ms++) {
        int row0 = m0 + mb + ms * 16 + g;
        #pragma unroll
        for (int ns = 0; ns < 4; ns++) {
            int col = j0 + nb + ns * 8 + tg * 2;
            if (row0 < NN)
                __stcs((float2*)&g_yb[(size_t)row0 * 512 + col],
                       make_float2(acc[ms][ns][0], acc[ms][ns][1]));
            if (row0 + 8 < NN)
                __stcs((float2*)&g_yb[(size_t)(row0 + 8) * 512 + col],
                       make_float2(acc[ms][ns][2], acc[ms][ns][3]));
        }
    }
}

// ======================= edge passes ==========================
__device__ __forceinline__ void red_add_v4(float* addr, float a, float b, float c, float d) {
    asm volatile("red.global.add.v4.f32 [%0], {%1, %2, %3, %4};"
                 :: "l"(addr), "f"(a), "f"(b), "f"(c), "f"(d) : "memory");
}

// -------- pass1: WARP-AUTONOMOUS. One warp owns one node end-to-end. --------
// No block barriers. Per node: cp.async its edge list into the warp's private
// smem slice, read yb row as 16 coalesced 128B lines into regs, compute the
// 32x32 relation table into the warp's private (padded) smem slice (this FMA
// phase hides the edge-fetch latency), then drain edges with only __syncwarp.
#define P1W_GRID 1184
#define XW_STRIDE 36    // padded row stride (floats): 16B-aligned, shifts banks by 4r
__global__ void __launch_bounds__(128) k_pass1w(const float* __restrict__ comps1) {
    __shared__ float sc1[RR * BBASES];       // 2 KB, block-shared read-only
    __shared__ float sxw[4][RR * XW_STRIDE]; // 4.6 KB per warp
    __shared__ int2  sev[4][64];             // 512 B per warp
    int tid = threadIdx.x;
    *(float4*)&sc1[tid << 2] = *(const float4*)&comps1[tid << 2];
    __syncthreads();

    int lane = tid & 31, w = tid >> 5;
    float* tw = sxw[w];
    int2*  ew = sev[w];
    int sub = lane >> 3;                 // 0..3: edge within quad
    int h4 = (lane & 7) << 2;            // h base 0,4,...,28
    int gw = blockIdx.x * 4 + w;         // global warp id = first node
    int NW = gridDim.x * 4;

    int start = 0, end = 0;
    if (gw < NN) { start = g_off[gw]; end = g_off[gw + 1]; }

    for (int n = gw; n < NN; n += NW) {
        int cnt = end - start;
        // 1. prefetch this node's edges (<=64; overflow falls back to LDG)
        int cc = cnt < 64 ? cnt : 64;
        if (lane < cc)      CP_ASYNC8(smem_u32(&ew[lane]),      &g_ev[start + lane]);
        if (lane + 32 < cc) CP_ASYNC8(smem_u32(&ew[lane + 32]), &g_ev[start + lane + 32]);
        CP_COMMIT();
        // 2. yb row: 16 coalesced lines (lane = h)
        float yreg[16];
        const float* ybp = &g_yb[(size_t)n * 512 + lane];
        #pragma unroll
        for (int b = 0; b < 16; b++) yreg[b] = __ldcs(&ybp[b * 32]);
        // 3. next node's offsets (pipelined)
        int n2 = n + NW;
        int start2 = 0, end2 = 0;
        if (n2 < NN) { start2 = g_off[n2]; end2 = g_off[n2 + 1]; }
        // 4. relation table: lane holds column h=lane for all 32 r
        #pragma unroll
        for (int r = 0; r < RR; r++) {
            float a = 0.f;
            #pragma unroll
            for (int b = 0; b < BBASES; b++)
                a += sc1[r * BBASES + b] * yreg[b];
            tw[r * XW_STRIDE + lane] = a;
        }
        // 5. edges arrived + table visible warp-wide
        CP_WAIT0();
        __syncwarp();
        // 6. drain edges: 4 per iter, 8 lanes each
        for (int base = 0; base < cnt; base += 4) {
            int i = base + sub;
            if (i < cnt) {
                int2 ev = (i < 64) ? ew[i] : __ldcs(&g_ev[start + i]);
                int r = ev.x >> 17;
                int f = ev.x & 0x1FFFF;
                float val = __int_as_float(ev.y);
                float4 x = *(const float4*)&tw[r * XW_STRIDE + h4];
                red_add_v4(&g_h1[f * HH + h4], val * x.x, val * x.y, val * x.z, val * x.w);
            }
        }
        __syncwarp();                     // protect tw/ew before next iteration
        start = start2; end = end2;
    }
}

// -------- pass2: R13 block version (port to warp-autonomous next if pass1 wins)
#define P2_GRID 888
#define SB2_STRIDE 528
__global__ void __launch_bounds__(128) k_pass2p(const float* __restrict__ comps2,
                                                const float* __restrict__ bases2,
                                                const float* __restrict__ bias1,
                                                float* __restrict__ out) {
    __shared__ float sb2[BBASES * SB2_STRIDE];
    __shared__ float sc2[RR * BBASES];
    __shared__ float sbias[HH];
    __shared__ float sh1[HH];
    __shared__ float st[BBASES * CC];
    __shared__ float sq[RR * CC];
    int tid = threadIdx.x;
    for (int i = tid; i < BBASES * HH * CC / 4; i += 128) {
        int b = (i << 2) >> 9;
        int o = (i << 2) & 511;
        *(float4*)&sb2[b * SB2_STRIDE + o] = *(const float4*)&bases2[b * 512 + o];
    }
    *(float4*)&sc2[tid << 2] = *(const float4*)&comps2[tid << 2];
    if (tid < HH) sbias[tid] = bias1[tid];
    __syncthreads();

    int lane = tid & 31;
    int w = tid >> 5;
    int sub = lane >> 2;
    int c0 = (lane & 3) << 2;

    for (int n = blockIdx.x; n < NN; n += gridDim.x) {
        if (tid < HH) sh1[tid] = fmaxf(g_h1[n * HH + tid] + sbias[tid], 0.f);
        __syncthreads();
        {
            int i = tid;
            int b = i >> 4, c = i & 15;
            float a0 = 0.f, a1 = 0.f;
            int b2 = (i + 128) >> 4, c2 = (i + 128) & 15;
            #pragma unroll
            for (int h = 0; h < HH; h++) {
                float hv = sh1[h];
                a0 += hv * sb2[b * SB2_STRIDE + h * CC + c];
                a1 += hv * sb2[b2 * SB2_STRIDE + h * CC + c2];
            }
            st[i] = a0;
            st[i + 128] = a1;
        }
        __syncthreads();
        #pragma unroll
        for (int k = 0; k < 4; k++) {
            int i = tid + k * 128;
            int r = i >> 4, c = i & 15;
            float a = 0.f;
            #pragma unroll
            for (int b = 0; b < BBASES; b++)
                a += sc2[r * BBASES + b] * st[b * CC + c];
            sq[i] = a;
        }
        __syncthreads();

        int start = g_off[n], end = g_off[n + 1];
        for (int base = start + (w << 3); base < end; base += 32) {
            int e = base + sub;
            if (e < end) {
                int2 ev = __ldcs(&g_ev[e]);
                int r = ev.x >> 17;
                int f = ev.x & 0x1FFFF;
                float val = __int_as_float(ev.y);
                float4 q = *(const float4*)&sq[r * CC + c0];
                red_add_v4(&out[f * CC + c0], val * q.x, val * q.y, val * q.z, val * q.w);
            }
        }
        __syncthreads();
    }
}

// -------- host: forked-stream launch (graph-capturable) --------
static cudaStream_t s_gemm = nullptr, s_node = nullptr;
static cudaEvent_t  e_root = nullptr, e_root2 = nullptr, e_gemm = nullptr, e_node = nullptr;

extern "C" void kernel_launch(void* const* d_in, const int* in_sizes, int n_in,
                              void* d_out, int out_size) {
    const float* emb    = (const float*)d_in[0];
    const float* comps1 = (const float*)d_in[1];
    const float* bases1 = (const float*)d_in[2];
    const float* comps2 = (const float*)d_in[3];
    const float* bases2 = (const float*)d_in[4];
    const float* bias1  = (const float*)d_in[5];
    const float* bias2  = (const float*)d_in[6];
    const int*   rel    = (const int*)d_in[7];
    const int*   fr     = (const int*)d_in[8];
    const int*   to     = (const int*)d_in[9];
    float* out = (float*)d_out;

    if (!s_gemm) {   // first call = correctness run (not captured)
        cudaStreamCreateWithFlags(&s_gemm, cudaStreamNonBlocking);
        cudaStreamCreateWithFlags(&s_node, cudaStreamNonBlocking);
        cudaEventCreateWithFlags(&e_root,  cudaEventDisableTiming);
        cudaEventCreateWithFlags(&e_root2, cudaEventDisableTiming);
        cudaEventCreateWithFlags(&e_gemm,  cudaEventDisableTiming);
        cudaEventCreateWithFlags(&e_node,  cudaEventDisableTiming);
        cudaFuncSetAttribute(k_gemm_hmma, cudaFuncAttributeMaxDynamicSharedMemorySize, HMM_SMEM);
    }

    cudaEventRecord(e_root, 0);
    cudaStreamWaitEvent(s_gemm, e_root, 0);
    cudaEventRecord(e_root2, 0);
    cudaStreamWaitEvent(s_node, e_root2, 0);

    k_prepB<<<256, 256, 0, s_gemm>>>(bases1);                   // [1] (s_gemm)
    k_init_edge<<<8192, 256>>>();                               // [2] (default)
    k_init_node<<<4096, 256, 0, s_node>>>(bias2, out);          // [3] (s_node)
    k_gemm_hmma<<<1563 * 4, 256, HMM_SMEM, s_gemm>>>(emb);      // [4] PROFILED
    k_deg<<<4096, 256>>>(rel, fr, to);                          // [5] (default)
    k_scan1<<<SCAN_BLOCKS, 1024>>>();
    k_scan2<<<1, 128>>>();
    k_scan3<<<SCAN_BLOCKS, 1024>>>();
    k_scatter<<<4096, 256>>>(rel, fr, to);

    cudaEventRecord(e_gemm, s_gemm);
    cudaEventRecord(e_node, s_node);
    cudaStreamWaitEvent(0, e_gemm, 0);
    cudaStreamWaitEvent(0, e_node, 0);

    k_pass1w<<<P1W_GRID, 128>>>(comps1);
    k_pass2p<<<P2_GRID, 128>>>(comps2, bases2, bias1, out);
}

// round 17
// speedup vs baseline: 1.6709x; 1.1981x over previous
#include <cuda_runtime.h>
#include <cuda_bf16.h>
#include <cstdint>

#define NN    100000   // nodes
#define RR    32       // relations
#define EE    3200000  // edges
#define EMBD  128      // embedding dim
#define HH    32       // hidden dim
#define BBASES 16      // num bases
#define CC    16       // output classes

#define SCAN_BLOCKS ((NN + 1023) / 1024)   // 98

// -------- scratch (static device globals) --------
__device__ float g_deg[RR * NN];                 // 12.8 MB
__device__ float g_h1[NN * HH];                  // 12.8 MB
__device__ float g_yb[NN * (BBASES * HH)];       // 204.8 MB
__device__ int   g_cnt[NN];
__device__ int   g_off[NN + 1];
__device__ int   g_pos[NN];
__device__ int   g_bsum[SCAN_BLOCKS];
__device__ int2  g_ev[EE];                       // 25.6 MB
__device__ unsigned short g_b1h[512 * 128];      // 128 KB  W bf16 hi, j-major [j][k]
__device__ unsigned short g_b1l[512 * 128];      // 128 KB  W bf16 lo

__device__ __forceinline__ uint32_t smem_u32(const void* p) {
    uint32_t a;
    asm("{ .reg .u64 t; cvta.to.shared.u64 t, %1; cvt.u32.u64 %0, t; }" : "=r"(a) : "l"(p));
    return a;
}
#define CP_ASYNC8(dst, src) \
    asm volatile("cp.async.ca.shared.global [%0], [%1], 8;" :: "r"(dst), "l"(src) : "memory")
#define CP_COMMIT() asm volatile("cp.async.commit_group;" ::: "memory")
#define CP_WAIT0()  asm volatile("cp.async.wait_group 0;" ::: "memory")

// ======================= small kernels ==========================
__global__ void k_init_edge() {
    int i = blockIdx.x * blockDim.x + threadIdx.x;
    int stride = gridDim.x * blockDim.x;
    for (int idx = i; idx < RR * NN; idx += stride) g_deg[idx] = 0.f;
    for (int idx = i; idx < NN; idx += stride) g_cnt[idx] = 0;
}

__global__ void k_init_node(const float* __restrict__ bias2, float* __restrict__ out) {
    int i = blockIdx.x * blockDim.x + threadIdx.x;
    int stride = gridDim.x * blockDim.x;
    for (int idx = i; idx < NN * HH; idx += stride) g_h1[idx] = 0.f;
    for (int idx = i; idx < NN * CC; idx += stride) out[idx] = bias2[idx & (CC - 1)];
}

// prep W: W[k][j] = bases1[b][k][h], j = b*32+h  ->  bf16 hi/lo, j-major [j][k]
__global__ void k_prepB(const float* __restrict__ bases1) {
    int i = blockIdx.x * blockDim.x + threadIdx.x;
    if (i >= 512 * 128) return;
    int j = i >> 7, k = i & 127;
    int b = j >> 5, h = j & 31;
    float v = bases1[(b * EMBD + k) * HH + h];
    __nv_bfloat16 hi = __float2bfloat16(v);
    float rem = v - __bfloat162float(hi);
    __nv_bfloat16 lo = __float2bfloat16(rem);
    g_b1h[i] = __bfloat16_as_ushort(hi);
    g_b1l[i] = __bfloat16_as_ushort(lo);
}

__global__ void k_deg(const int* __restrict__ rel, const int* __restrict__ fr,
                      const int* __restrict__ to) {
    int i = blockIdx.x * blockDim.x + threadIdx.x;
    int stride = gridDim.x * blockDim.x;
    for (int e = i; e < EE; e += stride) {
        atomicAdd(&g_deg[__ldcs(&rel[e]) * NN + __ldcs(&fr[e])], 1.0f);
        atomicAdd(&g_cnt[__ldcs(&to[e])], 1);
    }
}

__global__ void k_scan1() {
    __shared__ int s[1024];
    int tid = threadIdx.x;
    int i = blockIdx.x * 1024 + tid;
    int v = (i < NN) ? g_cnt[i] : 0;
    s[tid] = v;
    __syncthreads();
    #pragma unroll
    for (int d = 1; d < 1024; d <<= 1) {
        int t = (tid >= d) ? s[tid - d] : 0;
        __syncthreads();
        s[tid] += t;
        __syncthreads();
    }
    if (i < NN) g_off[i] = s[tid] - v;
    if (tid == 1023) g_bsum[blockIdx.x] = s[1023];
}

__global__ void k_scan2() {
    __shared__ int s[128];
    int tid = threadIdx.x;
    int v = (tid < SCAN_BLOCKS) ? g_bsum[tid] : 0;
    s[tid] = v;
    __syncthreads();
    #pragma unroll
    for (int d = 1; d < 128; d <<= 1) {
        int t = (tid >= d) ? s[tid - d] : 0;
        __syncthreads();
        s[tid] += t;
        __syncthreads();
    }
    if (tid < SCAN_BLOCKS) g_bsum[tid] = s[tid] - v;
}

__global__ void k_scan3() {
    int i = blockIdx.x * 1024 + threadIdx.x;
    if (i < NN) {
        int o = g_off[i] + g_bsum[i >> 10];
        g_off[i] = o;
        g_pos[i] = o;
    }
    if (i == 0) g_off[NN] = EE;
}

__global__ void k_scatter(const int* __restrict__ rel, const int* __restrict__ fr,
                          const int* __restrict__ to) {
    int i = blockIdx.x * blockDim.x + threadIdx.x;
    int stride = gridDim.x * blockDim.x;
    for (int e = i; e < EE; e += stride) {
        int r = __ldcs(&rel[e]), f = __ldcs(&fr[e]);
        int pos = atomicAdd(&g_pos[__ldcs(&to[e])], 1);
        float val = 1.0f / g_deg[r * NN + f];
        __stcs(&g_ev[pos], make_int2((r << 17) | f, __float_as_int(val)));
    }
}

// ============== HMMA GEMM: yb = emb @ W, bf16 double-split (hh+hl+lh) ==========
#define HMM_PAD   136
#define HMM_SMEM  (2 * 64 * HMM_PAD * 2 + 2 * 128 * HMM_PAD * 2)   // 104448 B

#define MMA16816(C, A_, B_) \
    asm volatile("mma.sync.aligned.m16n8k16.row.col.f32.bf16.bf16.f32 " \
        "{%0,%1,%2,%3}, {%4,%5,%6,%7}, {%8,%9}, {%0,%1,%2,%3};" \
        : "+f"((C)[0]), "+f"((C)[1]), "+f"((C)[2]), "+f"((C)[3]) \
        : "r"((A_)[0]), "r"((A_)[1]), "r"((A_)[2]), "r"((A_)[3]), \
          "r"((B_)[0]), "r"((B_)[1]))

__global__ void __launch_bounds__(256, 2) k_gemm_hmma(const float* __restrict__ A) {
    extern __shared__ unsigned short sm[];
    unsigned short* Ah = sm;                                    // 64x136
    unsigned short* Al = Ah + 64 * HMM_PAD;
    unsigned short* Bh = Al + 64 * HMM_PAD;                     // 128x136
    unsigned short* Bl = Bh + 128 * HMM_PAD;

    int tid = threadIdx.x;
    int mt = blockIdx.x >> 2;
    int jt = blockIdx.x & 3;
    int m0 = mt * 64;
    int j0 = jt * 128;

    #pragma unroll
    for (int i = 0; i < 8; i++) {
        int lin = tid + i * 256;
        int row = lin >> 5;
        int k = (lin & 31) << 2;
        int node = m0 + row;
        float4 v = make_float4(0.f, 0.f, 0.f, 0.f);
        if (node < NN) v = __ldcs((const float4*)(A + (size_t)node * EMBD + k));
        __nv_bfloat16 hx = __float2bfloat16(v.x), hy = __float2bfloat16(v.y);
        __nv_bfloat16 hz = __float2bfloat16(v.z), hw = __float2bfloat16(v.w);
        __nv_bfloat16 lx = __float2bfloat16(v.x - __bfloat162float(hx));
        __nv_bfloat16 ly = __float2bfloat16(v.y - __bfloat162float(hy));
        __nv_bfloat16 lz = __float2bfloat16(v.z - __bfloat162float(hz));
        __nv_bfloat16 lw = __float2bfloat16(v.w - __bfloat162float(hw));
        uint2 hp = make_uint2(
            (uint32_t)__bfloat16_as_ushort(hx) | ((uint32_t)__bfloat16_as_ushort(hy) << 16),
            (uint32_t)__bfloat16_as_ushort(hz) | ((uint32_t)__bfloat16_as_ushort(hw) << 16));
        uint2 lp = make_uint2(
            (uint32_t)__bfloat16_as_ushort(lx) | ((uint32_t)__bfloat16_as_ushort(ly) << 16),
            (uint32_t)__bfloat16_as_ushort(lz) | ((uint32_t)__bfloat16_as_ushort(lw) << 16));
        int o = row * HMM_PAD + k;
        *(uint2*)&Ah[o] = hp;
        *(uint2*)&Al[o] = lp;
    }
    #pragma unroll
    for (int i = 0; i < 8; i++) {
        int lin = tid + i * 256;
        int jr = lin >> 4;
        int k8 = (lin & 15) << 3;
        size_t src = (size_t)(j0 + jr) * 128 + k8;
        *(uint4*)&Bh[jr * HMM_PAD + k8] = *(const uint4*)&g_b1h[src];
        *(uint4*)&Bl[jr * HMM_PAD + k8] = *(const uint4*)&g_b1l[src];
    }
    __syncthreads();

    int lane = tid & 31, w = tid >> 5;
    int g = lane >> 2, tg = lane & 3;
    int mb = (w & 1) << 5;
    int nb = (w >> 1) << 5;

    float acc[2][4][4];
    #pragma unroll
    for (int ms = 0; ms < 2; ms++)
        #pragma unroll
        for (int ns = 0; ns < 4; ns++)
            #pragma unroll
            for (int q = 0; q < 4; q++) acc[ms][ns][q] = 0.f;

    #pragma unroll
    for (int ks = 0; ks < 8; ks++) {
        int k0 = ks * 16;
        uint32_t af[2][2][4];
        #pragma unroll
        for (int s = 0; s < 2; s++) {
            const unsigned short* Asrc = s ? Al : Ah;
            #pragma unroll
            for (int ms = 0; ms < 2; ms++) {
                int base = (mb + ms * 16 + g) * HMM_PAD + k0 + tg * 2;
                af[s][ms][0] = *(const uint32_t*)&Asrc[base];
                af[s][ms][1] = *(const uint32_t*)&Asrc[base + 8 * HMM_PAD];
                af[s][ms][2] = *(const uint32_t*)&Asrc[base + 8];
                af[s][ms][3] = *(const uint32_t*)&Asrc[base + 8 * HMM_PAD + 8];
            }
        }
        uint32_t bf[2][4][2];
        #pragma unroll
        for (int s = 0; s < 2; s++) {
            const unsigned short* Bsrc = s ? Bl : Bh;
            #pragma unroll
            for (int ns = 0; ns < 4; ns++) {
                int base = (nb + ns * 8 + g) * HMM_PAD + k0 + tg * 2;
                bf[s][ns][0] = *(const uint32_t*)&Bsrc[base];
                bf[s][ns][1] = *(const uint32_t*)&Bsrc[base + 8];
            }
        }
        #pragma unroll
        for (int ms = 0; ms < 2; ms++)
            #pragma unroll
            for (int ns = 0; ns < 4; ns++) {
                MMA16816(acc[ms][ns], af[0][ms], bf[0][ns]);   // hh
                MMA16816(acc[ms][ns], af[0][ms], bf[1][ns]);   // hl
                MMA16816(acc[ms][ns], af[1][ms], bf[0][ns]);   // lh
            }
    }

    #pragma unroll
    for (int ms = 0; ms < 2; ms++) {
        int row0 = m0 + mb + ms * 16 + g;
        #pragma unroll
        for (int ns = 0; ns < 4; ns++) {
            int col = j0 + nb + ns * 8 + tg * 2;
            if (row0 < NN)
                __stcs((float2*)&g_yb[(size_t)row0 * 512 + col],
                       make_float2(acc[ms][ns][0], acc[ms][ns][1]));
            if (row0 + 8 < NN)
                __stcs((float2*)&g_yb[(size_t)(row0 + 8) * 512 + col],
                       make_float2(acc[ms][ns][2], acc[ms][ns][3]));
        }
    }
}

// ======================= edge passes ==========================
__device__ __forceinline__ void red_add_v4(float* addr, float a, float b, float c, float d) {
    asm volatile("red.global.add.v4.f32 [%0], {%1, %2, %3, %4};"
                 :: "l"(addr), "f"(a), "f"(b), "f"(c), "f"(d) : "memory");
}

// -------- pass1: warp-autonomous (unchanged from R16 win) --------
#define P1W_GRID 1184
#define XW_STRIDE 36
__global__ void __launch_bounds__(128) k_pass1w(const float* __restrict__ comps1) {
    __shared__ float sc1[RR * BBASES];
    __shared__ float sxw[4][RR * XW_STRIDE];
    __shared__ int2  sev[4][64];
    int tid = threadIdx.x;
    *(float4*)&sc1[tid << 2] = *(const float4*)&comps1[tid << 2];
    __syncthreads();

    int lane = tid & 31, w = tid >> 5;
    float* tw = sxw[w];
    int2*  ew = sev[w];
    int sub = lane >> 3;
    int h4 = (lane & 7) << 2;
    int gw = blockIdx.x * 4 + w;
    int NW = gridDim.x * 4;

    int start = 0, end = 0;
    if (gw < NN) { start = g_off[gw]; end = g_off[gw + 1]; }

    for (int n = gw; n < NN; n += NW) {
        int cnt = end - start;
        int cc = cnt < 64 ? cnt : 64;
        if (lane < cc)      CP_ASYNC8(smem_u32(&ew[lane]),      &g_ev[start + lane]);
        if (lane + 32 < cc) CP_ASYNC8(smem_u32(&ew[lane + 32]), &g_ev[start + lane + 32]);
        CP_COMMIT();
        float yreg[16];
        const float* ybp = &g_yb[(size_t)n * 512 + lane];
        #pragma unroll
        for (int b = 0; b < 16; b++) yreg[b] = __ldcs(&ybp[b * 32]);
        int n2 = n + NW;
        int start2 = 0, end2 = 0;
        if (n2 < NN) { start2 = g_off[n2]; end2 = g_off[n2 + 1]; }
        #pragma unroll
        for (int r = 0; r < RR; r++) {
            float a = 0.f;
            #pragma unroll
            for (int b = 0; b < BBASES; b++)
                a += sc1[r * BBASES + b] * yreg[b];
            tw[r * XW_STRIDE + lane] = a;
        }
        CP_WAIT0();
        __syncwarp();
        for (int base = 0; base < cnt; base += 4) {
            int i = base + sub;
            if (i < cnt) {
                int2 ev = (i < 64) ? ew[i] : __ldcs(&g_ev[start + i]);
                int r = ev.x >> 17;
                int f = ev.x & 0x1FFFF;
                float val = __int_as_float(ev.y);
                float4 x = *(const float4*)&tw[r * XW_STRIDE + h4];
                red_add_v4(&g_h1[f * HH + h4], val * x.x, val * x.y, val * x.z, val * x.w);
            }
        }
        __syncwarp();
        start = start2; end = end2;
    }
}

// -------- pass2: WARP-AUTONOMOUS. One warp owns one node end-to-end. --------
// Dynamic smem layout (floats):
//   sb2   [16*528]  bases2 padded           = 8448
//   sc2   [512]     comps2
//   sbias [32]
//   per warp (x8): sh1[32], st[256] (c-major: st[c*16+b]), sq[512], sev 64xint2
#define SB2_STRIDE 528
#define P2W_WARPS 8
#define P2W_WSLICE (32 + 256 + 512 + 128)            // floats per warp = 928
#define P2W_SMEM ((8448 + 512 + 32 + P2W_WARPS * P2W_WSLICE) * 4)   // 65664 B
#define P2W_GRID 444
__global__ void __launch_bounds__(256) k_pass2w(const float* __restrict__ comps2,
                                                const float* __restrict__ bases2,
                                                const float* __restrict__ bias1,
                                                float* __restrict__ out) {
    extern __shared__ float dyn[];
    float* sb2   = dyn;
    float* sc2   = dyn + 8448;
    float* sbias = sc2 + 512;
    int tid = threadIdx.x;
    for (int i = tid; i < BBASES * HH * CC / 4; i += 256) {
        int b = (i << 2) >> 9;
        int o = (i << 2) & 511;
        *(float4*)&sb2[b * SB2_STRIDE + o] = *(const float4*)&bases2[b * 512 + o];
    }
    *(float2*)&sc2[tid << 1] = *(const float2*)&comps2[tid << 1];
    if (tid < HH) sbias[tid] = bias1[tid];
    __syncthreads();

    int lane = tid & 31, w = tid >> 5;
    float* wb  = sbias + 32 + w * P2W_WSLICE;
    float* h1w = wb;                 // 32
    float* stw = wb + 32;            // 256, c-major: stw[c*16+b]
    float* sqw = wb + 32 + 256;      // 512: sq[r*16+c]
    int2*  ew  = (int2*)(wb + 32 + 256 + 512);  // 64 records

    int sub = lane >> 2;             // 0..7: edge in octet
    int c0 = (lane & 3) << 2;        // c base for edge drain
    int rh = lane >> 4;              // 0/1: r-half for q compute
    int cq = lane & 15;              // c for q compute
    int tb  = lane >> 2;             // t-stage: b (first tile)
    int tcq = (lane & 3) << 2;       // t-stage: c base

    int gw = blockIdx.x * P2W_WARPS + w;
    int NW = gridDim.x * P2W_WARPS;
    int start = 0, end = 0;
    if (gw < NN) { start = g_off[gw]; end = g_off[gw + 1]; }

    for (int n = gw; n < NN; n += NW) {
        int cnt = end - start;
        int cc = cnt < 64 ? cnt : 64;
        if (lane < cc)      CP_ASYNC8(smem_u32(&ew[lane]),      &g_ev[start + lane]);
        if (lane + 32 < cc) CP_ASYNC8(smem_u32(&ew[lane + 32]), &g_ev[start + lane + 32]);
        CP_COMMIT();

        // h1 + relu into warp smem, then all 32 values into registers
        float hv = __ldcs(&g_h1[(size_t)n * HH + lane]);
        h1w[lane] = fmaxf(hv + sbias[lane], 0.f);
        int n2 = n + NW;
        int start2 = 0, end2 = 0;
        if (n2 < NN) { start2 = g_off[n2]; end2 = g_off[n2 + 1]; }
        __syncwarp();
        float h1r[HH];
        #pragma unroll
        for (int q = 0; q < 8; q++)
            *(float4*)&h1r[q << 2] = *(const float4*)&h1w[q << 2];

        // t-stage: lane computes 2 (b, c-quad) tiles via LDS.128 on sb2
        #pragma unroll
        for (int half = 0; half < 2; half++) {
            int b = tb + half * 8;
            float4 a4 = make_float4(0.f, 0.f, 0.f, 0.f);
            #pragma unroll
            for (int h = 0; h < HH; h++) {
                float4 b4 = *(const float4*)&sb2[b * SB2_STRIDE + h * CC + tcq];
                a4.x += h1r[h] * b4.x;
                a4.y += h1r[h] * b4.y;
                a4.z += h1r[h] * b4.z;
                a4.w += h1r[h] * b4.w;
            }
            stw[(tcq + 0) * 16 + b] = a4.x;
            stw[(tcq + 1) * 16 + b] = a4.y;
            stw[(tcq + 2) * 16 + b] = a4.z;
            stw[(tcq + 3) * 16 + b] = a4.w;
        }
        __syncwarp();

        // q-stage: lane (rh, cq) computes q[r][cq] for 16 r's.
        float4 st4[4];
        #pragma unroll
        for (int q = 0; q < 4; q++)
            st4[q] = *(const float4*)&stw[cq * 16 + (q << 2)];
        #pragma unroll
        for (int k = 0; k < 16; k++) {
            int r = rh * 16 + k;
            const float4* sc4 = (const float4*)&sc2[r * BBASES];
            float a = 0.f;
            #pragma unroll
            for (int q = 0; q < 4; q++) {
                float4 c4 = sc4[q];
                a += c4.x * st4[q].x + c4.y * st4[q].y + c4.z * st4[q].z + c4.w * st4[q].w;
            }
            sqw[r * CC + cq] = a;
        }
        CP_WAIT0();
        __syncwarp();

        // edge drain: 8 edges/iter, 4 lanes each (lane covers 4 c's)
        for (int base = 0; base < cnt; base += 8) {
            int i = base + sub;
            if (i < cnt) {
                int2 ev = (i < 64) ? ew[i] : __ldcs(&g_ev[start + i]);
                int r = ev.x >> 17;
                int f = ev.x & 0x1FFFF;
                float val = __int_as_float(ev.y);
                float4 q = *(const float4*)&sqw[r * CC + c0];
                red_add_v4(&out[f * CC + c0], val * q.x, val * q.y, val * q.z, val * q.w);
            }
        }
        __syncwarp();
        start = start2; end = end2;
    }
}

// -------- host: forked-stream launch (graph-capturable) --------
static cudaStream_t s_gemm = nullptr, s_node = nullptr;
static cudaEvent_t  e_root = nullptr, e_root2 = nullptr, e_gemm = nullptr, e_node = nullptr;

extern "C" void kernel_launch(void* const* d_in, const int* in_sizes, int n_in,
                              void* d_out, int out_size) {
    const float* emb    = (const float*)d_in[0];
    const float* comps1 = (const float*)d_in[1];
    const float* bases1 = (const float*)d_in[2];
    const float* comps2 = (const float*)d_in[3];
    const float* bases2 = (const float*)d_in[4];
    const float* bias1  = (const float*)d_in[5];
    const float* bias2  = (const float*)d_in[6];
    const int*   rel    = (const int*)d_in[7];
    const int*   fr     = (const int*)d_in[8];
    const int*   to     = (const int*)d_in[9];
    float* out = (float*)d_out;

    if (!s_gemm) {   // first call = correctness run (not captured)
        cudaStreamCreateWithFlags(&s_gemm, cudaStreamNonBlocking);
        cudaStreamCreateWithFlags(&s_node, cudaStreamNonBlocking);
        cudaEventCreateWithFlags(&e_root,  cudaEventDisableTiming);
        cudaEventCreateWithFlags(&e_root2, cudaEventDisableTiming);
        cudaEventCreateWithFlags(&e_gemm,  cudaEventDisableTiming);
        cudaEventCreateWithFlags(&e_node,  cudaEventDisableTiming);
        cudaFuncSetAttribute(k_gemm_hmma, cudaFuncAttributeMaxDynamicSharedMemorySize, HMM_SMEM);
        cudaFuncSetAttribute(k_pass2w, cudaFuncAttributeMaxDynamicSharedMemorySize, P2W_SMEM);
    }

    cudaEventRecord(e_root, 0);
    cudaStreamWaitEvent(s_gemm, e_root, 0);
    cudaEventRecord(e_root2, 0);
    cudaStreamWaitEvent(s_node, e_root2, 0);

    k_prepB<<<256, 256, 0, s_gemm>>>(bases1);                   // [1] (s_gemm)
    k_init_edge<<<8192, 256>>>();                               // [2] (default)
    k_init_node<<<4096, 256, 0, s_node>>>(bias2, out);          // [3] (s_node)
    k_gemm_hmma<<<1563 * 4, 256, HMM_SMEM, s_gemm>>>(emb);      // [4] PROFILED
    k_deg<<<4096, 256>>>(rel, fr, to);                          // [5] (default)
    k_scan1<<<SCAN_BLOCKS, 1024>>>();
    k_scan2<<<1, 128>>>();
    k_scan3<<<SCAN_BLOCKS, 1024>>>();
    k_scatter<<<4096, 256>>>(rel, fr, to);

    cudaEventRecord(e_gemm, s_gemm);
    cudaEventRecord(e_node, s_node);
    cudaStreamWaitEvent(0, e_gemm, 0);
    cudaStreamWaitEvent(0, e_node, 0);

    k_pass1w<<<P1W_GRID, 128>>>(comps1);
    k_pass2w<<<P2W_GRID, 256, P2W_SMEM>>>(comps2, bases2, bias1, out);
}